// round 10
// baseline (speedup 1.0000x reference)
#include <cuda_runtime.h>
#include <cstdint>

#define NN    8192
#define F_IN  256
#define NHID  128
#define EDGES 524288      // 2^19
#define KTOP  32
#define MAXD  512   // max supported degree per row (mean 64, sigma 8 -> safe)

// ---------------- device scratch (no allocations allowed) ----------------
__device__ float g_a[NN];
__device__ float g_b[NN];
__device__ int   g_count[NN];
__device__ int   g_cursor[NN];
__device__ int   g_start[NN];
__device__ float g_z[EDGES];       // bucket (unsorted within segment)
__device__ int   g_col[EDGES];
__device__ float g_zs[EDGES];      // sorted by (seg, -z)  == ref's zs
__device__ int   g_cols[EDGES];
// ReduceWindowRewriter(base=16) hierarchy: 2^19 -> 32768 -> 2048 -> 128 -> 8
__device__ float g_I1[EDGES];        // inner 16-scans of zs
__device__ float g_s1[EDGES / 16];   // 32768 block sums
__device__ float g_I2[EDGES / 16];   // inner 16-scans of s1
__device__ float g_s2[EDGES / 256];  // 2048
__device__ float g_I3[EDGES / 256];  // inner 16-scans of s2
__device__ float g_s3[EDGES / 4096]; // 128
__device__ float g_O4[EDGES / 4096]; // composed scan of s3 (level 4+5)
__device__ float g_O3[EDGES / 256];  // composed scan of s2
__device__ float g_O2[EDGES / 16];   // composed scan of s1

// cs[j] = (j>>4)==0 ? I1[j] : fl(O2[(j>>4)-1] + I1[j])
__device__ __forceinline__ float cs_at(int j) {
    int jb = j >> 4;
    float v = g_I1[j];
    return (jb == 0) ? v : __fadd_rn(g_O2[jb - 1], v);
}

// sequential ascending 16-fold within half-warp groups via shfl
__device__ __forceinline__ float fold16(float x, int lane) {
    int grp = lane & 16;          // 0 or 16: chunk base within warp
    int l15 = lane & 15;
    float acc = 0.f;
#pragma unroll
    for (int k = 0; k < 16; k++) {
        float v = __shfl_sync(0xffffffffu, x, grp + k);
        if (l15 >= k) acc = (k == 0) ? v : __fadd_rn(acc, v);
    }
    return acc;
}

// ---------------- kernel 0: zero-fill adjacency (268 MB streaming write) ---
__global__ void k_fill(float4* __restrict__ adj4) {
    size_t i = (size_t)blockIdx.x * blockDim.x + threadIdx.x;
    adj4[i] = make_float4(0.f, 0.f, 0.f, 0.f);
}

// ---------------- kernel 1: zero histogram counters ----------------
__global__ void k_zero_counts() {
    int i = blockIdx.x * blockDim.x + threadIdx.x;
    if (i < NN) g_count[i] = 0;
}

// ---------------- kernel 2: h = relu(x @ W1 + b1) ----------------
// (verified bitwise-identical to reference h — DO NOT TOUCH arithmetic)
__global__ void k_gemm_relu(const float* __restrict__ x,
                            const float* __restrict__ W1,
                            const float* __restrict__ b1,
                            float* __restrict__ h) {
    __shared__ float xs[64][33];
    __shared__ float ws[32][128];
    const int tid = threadIdx.x;
    const int tr = tid >> 5;
    const int tc = tid & 31;
    const int rowBase = blockIdx.x * 64;

    float acc[8][4];
#pragma unroll
    for (int i = 0; i < 8; i++)
#pragma unroll
        for (int j = 0; j < 4; j++) acc[i][j] = 0.f;

    for (int k0 = 0; k0 < F_IN; k0 += 32) {
#pragma unroll
        for (int l = 0; l < 8; l++) {
            int idx = tid + l * 256;
            int r = idx >> 5;
            int kk = idx & 31;
            xs[r][kk] = x[(size_t)(rowBase + r) * F_IN + k0 + kk];
        }
#pragma unroll
        for (int l = 0; l < 16; l++) {
            int idx = tid + l * 256;
            int kk = idx >> 7;
            int c = idx & 127;
            ws[kk][c] = W1[(size_t)(k0 + kk) * NHID + c];
        }
        __syncthreads();
#pragma unroll
        for (int kk = 0; kk < 32; kk++) {
            float4 b4 = *reinterpret_cast<const float4*>(&ws[kk][tc * 4]);
#pragma unroll
            for (int i = 0; i < 8; i++) {
                float av = xs[tr * 8 + i][kk];
                acc[i][0] += av * b4.x;
                acc[i][1] += av * b4.y;
                acc[i][2] += av * b4.z;
                acc[i][3] += av * b4.w;
            }
        }
        __syncthreads();
    }
#pragma unroll
    for (int i = 0; i < 8; i++) {
        int r = rowBase + tr * 8 + i;
#pragma unroll
        for (int j = 0; j < 4; j++) {
            int c = tc * 4 + j;
            float v = acc[i][j] + b1[c];
            h[(size_t)r * NHID + c] = fmaxf(v, 0.f);
        }
    }
}

// ---------------- kernel 3: per-node a, b via sequential ascending-k FMA ---
__global__ void k_ab(const float* __restrict__ h, const float* __restrict__ We) {
    int n = blockIdx.x * blockDim.x + threadIdx.x;
    if (n >= NN) return;
    const float4* hr = (const float4*)(h + (size_t)n * NHID);
    const float4* w1 = (const float4*)We;            // We[0:128]
    const float4* w2 = (const float4*)(We + NHID);   // We[128:256]
    float a = 0.f, b = 0.f;
#pragma unroll
    for (int i = 0; i < NHID / 4; i++) {
        float4 hv = hr[i];
        float4 wa = w1[i];
        float4 wb = w2[i];
        a = __fmaf_rn(hv.x, wa.x, a);
        a = __fmaf_rn(hv.y, wa.y, a);
        a = __fmaf_rn(hv.z, wa.z, a);
        a = __fmaf_rn(hv.w, wa.w, a);
        b = __fmaf_rn(hv.x, wb.x, b);
        b = __fmaf_rn(hv.y, wb.y, b);
        b = __fmaf_rn(hv.z, wb.z, b);
        b = __fmaf_rn(hv.w, wb.w, b);
    }
    g_a[n] = a;
    g_b[n] = b;
}

// ---------------- kernel 4: degree histogram ----------------
__global__ void k_hist(const int* __restrict__ rows) {
    int i = blockIdx.x * blockDim.x + threadIdx.x;
    if (i < EDGES) atomicAdd(&g_count[rows[i]], 1);
}

// ---------------- kernel 5: exclusive scan of counts (single block) --------
__global__ void k_scan() {
    __shared__ int sums[1024];
    int tid = threadIdx.x;
    int base = tid * 8;
    int local[8];
    int s = 0;
#pragma unroll
    for (int i = 0; i < 8; i++) { local[i] = s; s += g_count[base + i]; }
    sums[tid] = s;
    __syncthreads();
    for (int off = 1; off < 1024; off <<= 1) {
        int v = (tid >= off) ? sums[tid - off] : 0;
        __syncthreads();
        sums[tid] += v;
        __syncthreads();
    }
    int excl = (tid == 0) ? 0 : sums[tid - 1];
#pragma unroll
    for (int i = 0; i < 8; i++) {
        int st = excl + local[i];
        g_start[base + i] = st;
        g_cursor[base + i] = st;
    }
}

// ---------------- kernel 6: scatter edges into segment buckets -------------
// z replicates reference structure: fl(fl(a + b) + be)
__global__ void k_scatter(const int* __restrict__ ei, const float* __restrict__ be) {
    int j = blockIdx.x * blockDim.x + threadIdx.x;
    if (j >= EDGES) return;
    int r = ei[j];
    int c = ei[EDGES + j];
    int p = atomicAdd(&g_cursor[r], 1);
    g_z[p] = __fadd_rn(__fadd_rn(g_a[r], g_b[c]), be[0]);
    g_col[p] = c;
}

// ---------------- kernel 7: per-row descending sort -> global sorted arrays
__global__ void __launch_bounds__(128) k_rowsort() {
    __shared__ float zr[MAXD];
    __shared__ int   cr[MAXD];
    const int r = blockIdx.x;
    const int tid = threadIdx.x;
    int deg = g_count[r];
    if (deg > MAXD) deg = MAXD;
    if (deg == 0) return;
    const int st = g_start[r];
    for (int i = tid; i < deg; i += 128) {
        zr[i] = g_z[st + i];
        cr[i] = g_col[st + i];
    }
    __syncthreads();
    for (int i = tid; i < deg; i += 128) {
        float zi = zr[i];
        int rk = 0;
        for (int j = 0; j < deg; j++) {
            float zj = zr[j];
            rk += (zj > zi) || (zj == zi && j < i);
        }
        g_zs[st + rk] = zi;
        g_cols[st + rk] = cr[i];
    }
}

// -------- chunk-16 level 1: inner scans of zs + block sums -----------------
__global__ void k16_l1() {
    int j = blockIdx.x * blockDim.x + threadIdx.x;
    float acc = fold16(g_zs[j], threadIdx.x & 31);
    g_I1[j] = acc;
    if ((j & 15) == 15) g_s1[j >> 4] = acc;
}

// -------- level 2: inner scans of s1 (32768) + sums s2 (2048) --------------
__global__ void k16_l2() {
    int j = blockIdx.x * blockDim.x + threadIdx.x;
    float acc = fold16(g_s1[j], threadIdx.x & 31);
    g_I2[j] = acc;
    if ((j & 15) == 15) g_s2[j >> 4] = acc;
}

// -------- level 3: inner scans of s2 (2048) + sums s3 (128) ----------------
__global__ void k16_l3() {
    int j = blockIdx.x * blockDim.x + threadIdx.x;
    float acc = fold16(g_s2[j], threadIdx.x & 31);
    g_I3[j] = acc;
    if ((j & 15) == 15) g_s3[j >> 4] = acc;
}

// -------- levels 4+5: s3 (128) -> I4, s4 (8) -> native seq scan -> O4 ------
__global__ void __launch_bounds__(128) k16_top() {
    __shared__ float sI4[128];
    __shared__ float sO5[8];
    int t = threadIdx.x;
    float acc = fold16(g_s3[t], t & 31);
    sI4[t] = acc;
    __syncthreads();
    if (t == 0) {
        float c = 0.f;
#pragma unroll
        for (int m = 0; m < 8; m++) {
            float s4 = sI4[m * 16 + 15];
            c = (m == 0) ? s4 : __fadd_rn(c, s4);
            sO5[m] = c;
        }
    }
    __syncthreads();
    int tb = t >> 4;
    g_O4[t] = (tb == 0) ? sI4[t] : __fadd_rn(sO5[tb - 1], sI4[t]);
}

// -------- compose level 3: O3[i] = fl(O4[i/16-1] + I3[i]) ------------------
__global__ void k16_c3() {
    int i = blockIdx.x * blockDim.x + threadIdx.x;
    int ib = i >> 4;
    float v = g_I3[i];
    g_O3[i] = (ib == 0) ? v : __fadd_rn(g_O4[ib - 1], v);
}

// -------- compose level 2: O2[i] = fl(O3[i/16-1] + I2[i]) ------------------
__global__ void k16_c2() {
    int i = blockIdx.x * blockDim.x + threadIdx.x;
    int ib = i >> 4;
    float v = g_I2[i];
    g_O2[i] = (ib == 0) ? v : __fadd_rn(g_O3[ib - 1], v);
}

// ---------------- kernel 9: ref-exact tau + scores + dedup + topK + write -
__global__ void __launch_bounds__(128) k_tau(float* __restrict__ adj) {
    __shared__ int   s_kmax;
    __shared__ float s_pref;
    __shared__ int   s_cnt;
    __shared__ float pv[MAXD];
    __shared__ int   pc[MAXD];

    const int r = blockIdx.x;
    const int tid = threadIdx.x;
    int deg = g_count[r];
    if (deg > MAXD) deg = MAXD;
    if (deg == 0) return;
    const int st = g_start[r];

    if (tid == 0) {
        s_kmax = 1;
        // prefix[start] = fl(cs[start] - zs[start])
        s_pref = __fsub_rn(cs_at(st), g_zs[st]);
    }
    __syncthreads();
    const float pref = s_pref;

    // cond = fl(1 + fl((pos+1)*z)) > fl(cs[j] - pref); kmax = max pos+1 true
    int lk = 0;
    for (int i = tid; i < deg; i += 128) {
        float zi = g_zs[st + i];
        float segcs = __fsub_rn(cs_at(st + i), pref);
        float lhs = __fadd_rn(1.0f, __fmul_rn((float)(i + 1), zi));
        if (lhs > segcs) lk = (i + 1) > lk ? (i + 1) : lk;
    }
    if (lk > 0) atomicMax(&s_kmax, lk);
    __syncthreads();

    if (tid == 0) {
        int kmax = s_kmax;
        float sck = __fsub_rn(cs_at(st + kmax - 1), pref);
        float tau = __fdiv_rn(__fsub_rn(sck, 1.0f), (float)kmax);
        // collect distinct positive cells (dup (r,c) -> identical score)
        int cnt = 0;
        for (int i = 0; i < deg; i++) {
            float sc = fmaxf(__fsub_rn(g_zs[st + i], tau), 0.0f);
            if (sc > 0.f) {
                int c = g_cols[st + i];
                bool dup = false;
                for (int j = 0; j < cnt; j++) {
                    if (pc[j] == c) { dup = true; break; }
                }
                if (!dup) { pc[cnt] = c; pv[cnt] = sc; cnt++; }
            }
        }
        s_cnt = cnt;
    }
    __syncthreads();
    const int cnt = s_cnt;

    // top-K counting rule: keep iff #{cells strictly greater} < KTOP
    for (int i = tid; i < cnt; i += 128) {
        float v = pv[i];
        int ng = 0;
        for (int j = 0; j < cnt; j++) ng += (pv[j] > v);
        if (ng < KTOP) adj[(size_t)r * NN + pc[i]] = v;
    }
}

// ---------------- launcher ----------------
extern "C" void kernel_launch(void* const* d_in, const int* in_sizes, int n_in,
                              void* d_out, int out_size) {
    const float* x  = (const float*)d_in[0];
    const int*   ei = (const int*)d_in[1];
    const float* W1 = (const float*)d_in[2];
    const float* b1 = (const float*)d_in[3];
    const float* We = (const float*)d_in[4];
    const float* be = (const float*)d_in[5];

    float* out = (float*)d_out;
    float* h   = out;                                            // first N*NHID floats
    float* adj = out + ((size_t)out_size - (size_t)NN * NN);     // last N*N floats

    k_fill<<<(NN * (size_t)NN / 4) / 256, 256>>>((float4*)adj);
    k_zero_counts<<<NN / 256, 256>>>();
    k_gemm_relu<<<NN / 64, 256>>>(x, W1, b1, h);
    k_ab<<<NN / 256, 256>>>(h, We);
    k_hist<<<EDGES / 256, 256>>>(ei);
    k_scan<<<1, 1024>>>();
    k_scatter<<<EDGES / 256, 256>>>(ei, be);
    k_rowsort<<<NN, 128>>>();
    k16_l1<<<EDGES / 256, 256>>>();
    k16_l2<<<(EDGES / 16) / 256, 256>>>();
    k16_l3<<<(EDGES / 256) / 256, 256>>>();
    k16_top<<<1, 128>>>();
    k16_c3<<<(EDGES / 256) / 256, 256>>>();
    k16_c2<<<(EDGES / 16) / 256, 256>>>();
    k_tau<<<NN, 128>>>(adj);
}